// round 2
// baseline (speedup 1.0000x reference)
#include <cuda_runtime.h>
#include <math.h>

#define N_NODES 50000
#define N_EDGES 1600000
#define DIM     128
#define RC      5.0f
#define DEPTH   3

#define SCAN_BLK 1024
#define N_CHUNKS ((N_NODES + SCAN_BLK - 1) / SCAN_BLK)   // 49

// ---------------- persistent device scratch (no allocation APIs) -------------
__device__ int   g_counts[N_NODES];
__device__ int   g_fill[N_NODES];
__device__ int   g_rowptr[N_NODES + 1];
__device__ int   g_bsum[N_CHUNKS];
__device__ int   g_boff[N_CHUNKS];
__device__ int   g_csr_src[N_EDGES];
__device__ float g_csr_f[N_EDGES];
__device__ float g_cur[N_NODES * DIM];   // layer output (layers 0,1)
__device__ float g_x[N_NODES * DIM];     // x = segment_sum + v  (GEMM input)

// ---------------------------------------------------------------------------
__global__ void k_zero()
{
    int i = blockIdx.x * blockDim.x + threadIdx.x;
    if (i < N_NODES) { g_counts[i] = 0; g_fill[i] = 0; }
}

__global__ void k_hist(const int* __restrict__ dst)
{
    int e = blockIdx.x * blockDim.x + threadIdx.x;
    if (e < N_EDGES) atomicAdd(&g_counts[dst[e]], 1);
}

// per-chunk inclusive scan
__global__ void k_scan1()
{
    __shared__ int s[SCAN_BLK];
    int t = threadIdx.x;
    int i = blockIdx.x * SCAN_BLK + t;
    s[t] = (i < N_NODES) ? g_counts[i] : 0;
    __syncthreads();
    for (int off = 1; off < SCAN_BLK; off <<= 1) {
        int add = (t >= off) ? s[t - off] : 0;
        __syncthreads();
        s[t] += add;
        __syncthreads();
    }
    if (i < N_NODES) g_rowptr[i + 1] = s[t];
    if (t == SCAN_BLK - 1) g_bsum[blockIdx.x] = s[t];
}

__global__ void k_scan2()
{
    if (threadIdx.x == 0) {
        g_rowptr[0] = 0;
        int run = 0;
        for (int c = 0; c < N_CHUNKS; c++) { g_boff[c] = run; run += g_bsum[c]; }
    }
}

__global__ void k_scan3()
{
    int i = blockIdx.x * blockDim.x + threadIdx.x;
    if (i < N_NODES) g_rowptr[i + 1] += g_boff[i / SCAN_BLK];
}

// scatter edges into CSR order; fold the edge envelope in here (computed once)
__global__ void k_fill(const int* __restrict__ src, const int* __restrict__ dst,
                       const float* __restrict__ e_in,
                       const float* __restrict__ rs, const float* __restrict__ sigma)
{
    int e = blockIdx.x * blockDim.x + threadIdx.x;
    if (e >= N_EDGES) return;
    int n    = dst[e];
    int slot = atomicAdd(&g_fill[n], 1);
    int p    = g_rowptr[n] + slot;

    float r   = e_in[e];
    float d   = r - rs[0];
    float sg  = sigma[0];
    float gau = expf(-(d * d) / (sg * sg));
    float cut = (r < RC) ? 0.5f * cosf(0.62831853071795864769f * r) : 0.0f; // pi/RC
    g_csr_src[p] = src[e];
    g_csr_f[p]   = gau * cut;
}

// one warp per node: x[n] = v[n] + sum_{edges->n} f * in[src]
__global__ void k_aggregate(const float* __restrict__ v, int use_cur)
{
    int gtid = blockIdx.x * blockDim.x + threadIdx.x;
    int node = gtid >> 5;
    int lane = gtid & 31;
    if (node >= N_NODES) return;

    const float* in = use_cur ? g_cur : v;
    int p0 = g_rowptr[node];
    int p1 = g_rowptr[node + 1];

    float4 acc = make_float4(0.f, 0.f, 0.f, 0.f);
    for (int p = p0; p < p1; p++) {
        int   s  = __ldg(&g_csr_src[p]);
        float fv = __ldg(&g_csr_f[p]);
        float4 u = *reinterpret_cast<const float4*>(in + (size_t)s * DIM + lane * 4);
        acc.x += fv * u.x; acc.y += fv * u.y; acc.z += fv * u.z; acc.w += fv * u.w;
    }
    float4 vv = *reinterpret_cast<const float4*>(v + (size_t)node * DIM + lane * 4);
    acc.x += vv.x; acc.y += vv.y; acc.z += vv.z; acc.w += vv.w;
    *reinterpret_cast<float4*>(g_x + (size_t)node * DIM + lane * 4) = acc;
}

// out = relu(x @ A^T + b).  Block: 32x8 threads, 64 rows per block.
// SMEM: A transposed (As[k][j], 64KB) + x tile (64x128, 32KB) = 96KB dynamic.
#define ROWS_PER_BLK 64
__global__ void __launch_bounds__(256, 2)
k_linear(const float* __restrict__ A, const float* __restrict__ b,
         float* __restrict__ dout, int last)
{
    extern __shared__ float smem[];
    float* As = smem;                  // 128*128
    float* xs = smem + DIM * DIM;      // 64*128

    int tx  = threadIdx.x;             // 0..31  (column quad)
    int ty  = threadIdx.y;             // 0..7   (row octet)
    int tid = ty * 32 + tx;

    // load A transposed: As[k*128 + j] = A[j*128 + k]
    for (int idx = tid; idx < DIM * DIM; idx += 256) {
        int k = idx >> 7, j = idx & 127;
        As[idx] = A[j * DIM + k];
    }
    int row0 = blockIdx.x * ROWS_PER_BLK;
    for (int idx = tid; idx < ROWS_PER_BLK * DIM; idx += 256) {
        int r = idx >> 7;
        xs[idx] = (row0 + r < N_NODES) ? g_x[(size_t)(row0 + r) * DIM + (idx & 127)] : 0.f;
    }
    __syncthreads();

    float4 acc[8];
#pragma unroll
    for (int r = 0; r < 8; r++) acc[r] = make_float4(0.f, 0.f, 0.f, 0.f);

    const float4* As4 = reinterpret_cast<const float4*>(As);
    const float*  xrow = xs + (ty * 8) * DIM;

#pragma unroll 8
    for (int k = 0; k < DIM; k++) {
        float4 a = As4[k * 32 + tx];
#pragma unroll
        for (int r = 0; r < 8; r++) {
            float xv = xrow[r * DIM + k];
            acc[r].x += a.x * xv;
            acc[r].y += a.y * xv;
            acc[r].z += a.z * xv;
            acc[r].w += a.w * xv;
        }
    }

    float4 bb = *reinterpret_cast<const float4*>(b + tx * 4);
    float* out = last ? dout : g_cur;
#pragma unroll
    for (int r = 0; r < 8; r++) {
        int row = row0 + ty * 8 + r;
        if (row < N_NODES) {
            float4 o;
            o.x = fmaxf(acc[r].x + bb.x, 0.f);
            o.y = fmaxf(acc[r].y + bb.y, 0.f);
            o.z = fmaxf(acc[r].z + bb.z, 0.f);
            o.w = fmaxf(acc[r].w + bb.w, 0.f);
            *reinterpret_cast<float4*>(out + (size_t)row * DIM + tx * 4) = o;
        }
    }
}

// ---------------------------------------------------------------------------
extern "C" void kernel_launch(void* const* d_in, const int* in_sizes, int n_in,
                              void* d_out, int out_size)
{
    const float* v     = (const float*)d_in[0];
    const float* e     = (const float*)d_in[1];
    const int*   src   = (const int*)d_in[2];
    const int*   dst   = (const int*)d_in[3];
    const float* A_w   = (const float*)d_in[4];
    const float* A_b   = (const float*)d_in[5];
    const float* rs    = (const float*)d_in[6];
    const float* sigma = (const float*)d_in[7];
    float* out = (float*)d_out;

    (void)in_sizes; (void)n_in; (void)out_size;

    const int SMEM_LIN = (DIM * DIM + ROWS_PER_BLK * DIM) * (int)sizeof(float); // 96KB
    cudaFuncSetAttribute(k_linear, cudaFuncAttributeMaxDynamicSharedMemorySize, SMEM_LIN);

    int gN = (N_NODES + 255) / 256;
    int gE = (N_EDGES + 255) / 256;

    // build CSR (per launch; inputs are constant so this is deterministic work)
    k_zero <<<gN, 256>>>();
    k_hist <<<gE, 256>>>(dst);
    k_scan1<<<N_CHUNKS, SCAN_BLK>>>();
    k_scan2<<<1, 32>>>();
    k_scan3<<<gN, 256>>>();
    k_fill <<<gE, 256>>>(src, dst, e, rs, sigma);

    int aggBlocks = (N_NODES * 32 + 255) / 256;           // warp per node
    int linBlocks = (N_NODES + ROWS_PER_BLK - 1) / ROWS_PER_BLK;
    dim3 linDim(32, 8);

    for (int d = 0; d < DEPTH; d++) {
        k_aggregate<<<aggBlocks, 256>>>(v, d > 0 ? 1 : 0);
        k_linear<<<linBlocks, linDim, SMEM_LIN>>>(A_w, A_b, out, d == DEPTH - 1 ? 1 : 0);
    }
}

// round 3
// speedup vs baseline: 1.0768x; 1.0768x over previous
#include <cuda_runtime.h>
#include <cuda_fp16.h>
#include <math.h>

#define N_NODES 50000
#define N_EDGES 1600000
#define DIM     128
#define RC      5.0f
#define DEPTH   3

#define SCAN_BLK 1024
#define N_CHUNKS ((N_NODES + SCAN_BLK - 1) / SCAN_BLK)   // 49

// ---------------- persistent device scratch (no allocation APIs) -------------
__device__ int    g_counts[N_NODES];
__device__ int    g_fill[N_NODES];
__device__ int    g_rowptr[N_NODES + 1];
__device__ int    g_bsum[N_CHUNKS];
__device__ int2   g_csr[N_EDGES];               // (src, f bits) packed, one 8B load/edge
__device__ __half g_curh[N_NODES * DIM];        // fp16 copy of current features (gather source)
__device__ float  g_x[N_NODES * DIM];           // x = segment_sum + v  (GEMM input, fp32)

// ---------------------------------------------------------------------------
__global__ void k_zero()
{
    int i = blockIdx.x * blockDim.x + threadIdx.x;
    if (i < N_NODES) { g_counts[i] = 0; g_fill[i] = 0; }
    if (i == 0) g_rowptr[0] = 0;
}

__global__ void k_hist(const int* __restrict__ dst)
{
    int e = blockIdx.x * blockDim.x + threadIdx.x;
    if (e < N_EDGES) atomicAdd(&g_counts[dst[e]], 1);
}

// per-chunk inclusive scan
__global__ void k_scan1()
{
    __shared__ int s[SCAN_BLK];
    int t = threadIdx.x;
    int i = blockIdx.x * SCAN_BLK + t;
    s[t] = (i < N_NODES) ? g_counts[i] : 0;
    __syncthreads();
    for (int off = 1; off < SCAN_BLK; off <<= 1) {
        int add = (t >= off) ? s[t - off] : 0;
        __syncthreads();
        s[t] += add;
        __syncthreads();
    }
    if (i < N_NODES) g_rowptr[i + 1] = s[t];
    if (t == SCAN_BLK - 1) g_bsum[blockIdx.x] = s[t];
}

// add prefix of chunk sums; chunk offset computed with a parallel tree reduce
__global__ void k_scan3()
{
    __shared__ int sb[64];
    int t = threadIdx.x;
    if (t < 64) sb[t] = (t < (int)blockIdx.x && t < N_CHUNKS) ? g_bsum[t] : 0;
    __syncthreads();
    for (int o = 32; o > 0; o >>= 1) {
        if (t < o) sb[t] += sb[t + o];
        __syncthreads();
    }
    int off = sb[0];
    int i = blockIdx.x * SCAN_BLK + t;
    if (i < N_NODES) g_rowptr[i + 1] += off;
}

// scatter edges into CSR order; fold the edge envelope in here (computed once)
__global__ void k_fill(const int* __restrict__ src, const int* __restrict__ dst,
                       const float* __restrict__ e_in,
                       const float* __restrict__ rs, const float* __restrict__ sigma)
{
    int e = blockIdx.x * blockDim.x + threadIdx.x;
    if (e >= N_EDGES) return;
    int n    = dst[e];
    int slot = atomicAdd(&g_fill[n], 1);
    int p    = g_rowptr[n] + slot;

    float r   = e_in[e];
    float d   = r - rs[0];
    float sg  = sigma[0];
    float gau = expf(-(d * d) / (sg * sg));
    float cut = (r < RC) ? 0.5f * cosf(0.62831853071795864769f * r) : 0.0f; // pi/RC
    g_csr[p] = make_int2(src[e], __float_as_int(gau * cut));
}

// initial fp16 copy of v (layer-0 gather source)
__global__ void k_v2h(const float* __restrict__ v)
{
    int i = blockIdx.x * blockDim.x + threadIdx.x;     // quad index
    if (i >= N_NODES * 32) return;
    float4 f = reinterpret_cast<const float4*>(v)[i];
    __half2 h0 = __floats2half2_rn(f.x, f.y);
    __half2 h1 = __floats2half2_rn(f.z, f.w);
    uint2 raw;
    raw.x = *reinterpret_cast<unsigned*>(&h0);
    raw.y = *reinterpret_cast<unsigned*>(&h1);
    reinterpret_cast<uint2*>(g_curh)[i] = raw;
}

// one warp per node: x[n] = v[n] + sum_{edges->n} f * curh[src]   (fp16 gather, fp32 acc)
__global__ void k_aggregate(const float* __restrict__ v)
{
    int gtid = blockIdx.x * blockDim.x + threadIdx.x;
    int node = gtid >> 5;
    int lane = gtid & 31;
    if (node >= N_NODES) return;

    int p0 = __ldg(&g_rowptr[node]);
    int p1 = __ldg(&g_rowptr[node + 1]);

    const uint2* in = reinterpret_cast<const uint2*>(g_curh);  // 4 halfs per uint2, 32/row
    float4 acc = make_float4(0.f, 0.f, 0.f, 0.f);

    int p = p0;
    for (; p + 1 < p1; p += 2) {
        int2 m0 = __ldg(&g_csr[p]);
        int2 m1 = __ldg(&g_csr[p + 1]);
        uint2 r0 = __ldg(&in[(size_t)m0.x * 32 + lane]);
        uint2 r1 = __ldg(&in[(size_t)m1.x * 32 + lane]);
        float f0 = __int_as_float(m0.y);
        float f1 = __int_as_float(m1.y);
        float2 a = __half22float2(*reinterpret_cast<__half2*>(&r0.x));
        float2 b = __half22float2(*reinterpret_cast<__half2*>(&r0.y));
        acc.x += f0 * a.x; acc.y += f0 * a.y; acc.z += f0 * b.x; acc.w += f0 * b.y;
        float2 c = __half22float2(*reinterpret_cast<__half2*>(&r1.x));
        float2 d = __half22float2(*reinterpret_cast<__half2*>(&r1.y));
        acc.x += f1 * c.x; acc.y += f1 * c.y; acc.z += f1 * d.x; acc.w += f1 * d.y;
    }
    if (p < p1) {
        int2 m0 = __ldg(&g_csr[p]);
        uint2 r0 = __ldg(&in[(size_t)m0.x * 32 + lane]);
        float f0 = __int_as_float(m0.y);
        float2 a = __half22float2(*reinterpret_cast<__half2*>(&r0.x));
        float2 b = __half22float2(*reinterpret_cast<__half2*>(&r0.y));
        acc.x += f0 * a.x; acc.y += f0 * a.y; acc.z += f0 * b.x; acc.w += f0 * b.y;
    }

    float4 vv = *reinterpret_cast<const float4*>(v + (size_t)node * DIM + lane * 4);
    acc.x += vv.x; acc.y += vv.y; acc.z += vv.z; acc.w += vv.w;
    *reinterpret_cast<float4*>(g_x + (size_t)node * DIM + lane * 4) = acc;
}

// out = relu(x @ A^T + b).  Block: 32x8 threads, 64 rows per block.
// Non-last layers also emit the fp16 copy for the next gather.
#define ROWS_PER_BLK 64
__global__ void __launch_bounds__(256, 2)
k_linear(const float* __restrict__ A, const float* __restrict__ b,
         float* __restrict__ dout, int last)
{
    extern __shared__ float smem[];
    float* As = smem;                  // 128*128
    float* xs = smem + DIM * DIM;      // 64*128

    int tx  = threadIdx.x;             // 0..31  (column quad)
    int ty  = threadIdx.y;             // 0..7   (row octet)
    int tid = ty * 32 + tx;

    // load A transposed: As[k*128 + j] = A[j*128 + k]
    for (int idx = tid; idx < DIM * DIM; idx += 256) {
        int k = idx >> 7, j = idx & 127;
        As[idx] = A[j * DIM + k];
    }
    int row0 = blockIdx.x * ROWS_PER_BLK;
    for (int idx = tid; idx < ROWS_PER_BLK * DIM; idx += 256) {
        int r = idx >> 7;
        xs[idx] = (row0 + r < N_NODES) ? g_x[(size_t)(row0 + r) * DIM + (idx & 127)] : 0.f;
    }
    __syncthreads();

    float4 acc[8];
#pragma unroll
    for (int r = 0; r < 8; r++) acc[r] = make_float4(0.f, 0.f, 0.f, 0.f);

    const float4* As4 = reinterpret_cast<const float4*>(As);
    const float*  xrow = xs + (ty * 8) * DIM;

#pragma unroll 8
    for (int k = 0; k < DIM; k++) {
        float4 a = As4[k * 32 + tx];
#pragma unroll
        for (int r = 0; r < 8; r++) {
            float xv = xrow[r * DIM + k];
            acc[r].x += a.x * xv;
            acc[r].y += a.y * xv;
            acc[r].z += a.z * xv;
            acc[r].w += a.w * xv;
        }
    }

    float4 bb = *reinterpret_cast<const float4*>(b + tx * 4);
#pragma unroll
    for (int r = 0; r < 8; r++) {
        int row = row0 + ty * 8 + r;
        if (row < N_NODES) {
            float4 o;
            o.x = fmaxf(acc[r].x + bb.x, 0.f);
            o.y = fmaxf(acc[r].y + bb.y, 0.f);
            o.z = fmaxf(acc[r].z + bb.z, 0.f);
            o.w = fmaxf(acc[r].w + bb.w, 0.f);
            if (last) {
                *reinterpret_cast<float4*>(dout + (size_t)row * DIM + tx * 4) = o;
            } else {
                __half2 h0 = __floats2half2_rn(o.x, o.y);
                __half2 h1 = __floats2half2_rn(o.z, o.w);
                uint2 raw;
                raw.x = *reinterpret_cast<unsigned*>(&h0);
                raw.y = *reinterpret_cast<unsigned*>(&h1);
                reinterpret_cast<uint2*>(g_curh)[row * 32 + tx] = raw;
            }
        }
    }
}

// ---------------------------------------------------------------------------
extern "C" void kernel_launch(void* const* d_in, const int* in_sizes, int n_in,
                              void* d_out, int out_size)
{
    const float* v     = (const float*)d_in[0];
    const float* e     = (const float*)d_in[1];
    const int*   src   = (const int*)d_in[2];
    const int*   dst   = (const int*)d_in[3];
    const float* A_w   = (const float*)d_in[4];
    const float* A_b   = (const float*)d_in[5];
    const float* rs    = (const float*)d_in[6];
    const float* sigma = (const float*)d_in[7];
    float* out = (float*)d_out;

    (void)in_sizes; (void)n_in; (void)out_size;

    const int SMEM_LIN = (DIM * DIM + ROWS_PER_BLK * DIM) * (int)sizeof(float); // 96KB
    cudaFuncSetAttribute(k_linear, cudaFuncAttributeMaxDynamicSharedMemorySize, SMEM_LIN);

    int gN = (N_NODES + 255) / 256;
    int gE = (N_EDGES + 255) / 256;

    // build CSR (per launch; inputs are constant so this is deterministic work)
    k_zero <<<gN, 256>>>();
    k_hist <<<gE, 256>>>(dst);
    k_scan1<<<N_CHUNKS, SCAN_BLK>>>();
    k_scan3<<<N_CHUNKS, SCAN_BLK>>>();
    k_fill <<<gE, 256>>>(src, dst, e, rs, sigma);
    k_v2h  <<<(N_NODES * 32 + 255) / 256, 256>>>(v);

    int aggBlocks = (N_NODES * 32 + 255) / 256;           // warp per node
    int linBlocks = (N_NODES + ROWS_PER_BLK - 1) / ROWS_PER_BLK;
    dim3 linDim(32, 8);

    for (int d = 0; d < DEPTH; d++) {
        k_aggregate<<<aggBlocks, 256>>>(v);
        k_linear<<<linBlocks, linDim, SMEM_LIN>>>(A_w, A_b, out, d == DEPTH - 1 ? 1 : 0);
    }
}

// round 4
// speedup vs baseline: 1.1068x; 1.0278x over previous
#include <cuda_runtime.h>
#include <cuda_fp16.h>
#include <math.h>

#define N_NODES 50000
#define N_EDGES 1600000
#define DIM     128
#define RC      5.0f
#define DEPTH   3

#define SCAN_BLK 1024
#define N_CHUNKS ((N_NODES + SCAN_BLK - 1) / SCAN_BLK)   // 49

// ---------------- persistent device scratch (no allocation APIs) -------------
__device__ int    g_counts[N_NODES];
__device__ int    g_rowptr[N_NODES + 1];
__device__ int    g_bsum[N_CHUNKS];
__device__ int    g_slot[N_EDGES];              // per-edge slot within its dst list
__device__ int2   g_csr[N_EDGES];               // (src, f bits) packed, one 8B load/edge
__device__ __half g_curh[N_NODES * DIM];        // fp16 copy of current features (gather source)
__device__ float  g_x[N_NODES * DIM];           // x = segment_sum + v  (GEMM input, fp32)

// ---------------------------------------------------------------------------
__global__ void k_zero()
{
    int i = blockIdx.x * blockDim.x + threadIdx.x;
    if (i < N_NODES) g_counts[i] = 0;
    if (i == 0) g_rowptr[0] = 0;
}

// histogram + slot assignment in one atomic pass
__global__ void k_hist(const int* __restrict__ dst)
{
    int e = blockIdx.x * blockDim.x + threadIdx.x;
    if (e < N_EDGES) g_slot[e] = atomicAdd(&g_counts[dst[e]], 1);
}

// per-chunk inclusive scan
__global__ void k_scan1()
{
    __shared__ int s[SCAN_BLK];
    int t = threadIdx.x;
    int i = blockIdx.x * SCAN_BLK + t;
    s[t] = (i < N_NODES) ? g_counts[i] : 0;
    __syncthreads();
    for (int off = 1; off < SCAN_BLK; off <<= 1) {
        int add = (t >= off) ? s[t - off] : 0;
        __syncthreads();
        s[t] += add;
        __syncthreads();
    }
    if (i < N_NODES) g_rowptr[i + 1] = s[t];
    if (t == SCAN_BLK - 1) g_bsum[blockIdx.x] = s[t];
}

// add prefix of chunk sums; chunk offset via tree reduce (no serial kernel)
__global__ void k_scan3()
{
    __shared__ int sb[64];
    int t = threadIdx.x;
    if (t < 64) sb[t] = (t < (int)blockIdx.x && t < N_CHUNKS) ? g_bsum[t] : 0;
    __syncthreads();
    for (int o = 32; o > 0; o >>= 1) {
        if (t < o) sb[t] += sb[t + o];
        __syncthreads();
    }
    int off = sb[0];
    int i = blockIdx.x * SCAN_BLK + t;
    if (i < N_NODES) g_rowptr[i + 1] += off;
}

// scatter edges into CSR order (atomic-free: slot precomputed in k_hist);
// fold the edge envelope in here (computed once)
__global__ void k_fill(const int* __restrict__ src, const int* __restrict__ dst,
                       const float* __restrict__ e_in,
                       const float* __restrict__ rs, const float* __restrict__ sigma)
{
    int e = blockIdx.x * blockDim.x + threadIdx.x;
    if (e >= N_EDGES) return;
    int n = dst[e];
    int p = g_rowptr[n] + g_slot[e];

    float r   = e_in[e];
    float d   = r - rs[0];
    float sg  = sigma[0];
    float gau = expf(-(d * d) / (sg * sg));
    float cut = (r < RC) ? 0.5f * cosf(0.62831853071795864769f * r) : 0.0f; // pi/RC
    g_csr[p] = make_int2(src[e], __float_as_int(gau * cut));
}

// initial fp16 copy of v (layer-0 gather source)
__global__ void k_v2h(const float* __restrict__ v)
{
    int i = blockIdx.x * blockDim.x + threadIdx.x;     // quad index
    if (i >= N_NODES * 32) return;
    float4 f = reinterpret_cast<const float4*>(v)[i];
    __half2 h0 = __floats2half2_rn(f.x, f.y);
    __half2 h1 = __floats2half2_rn(f.z, f.w);
    uint2 raw;
    raw.x = *reinterpret_cast<unsigned*>(&h0);
    raw.y = *reinterpret_cast<unsigned*>(&h1);
    reinterpret_cast<uint2*>(g_curh)[i] = raw;
}

// one warp per node: x[n] = v[n] + sum_{edges->n} f * curh[src]
// Meta for 32 edges is loaded with ONE coalesced int2 load and staged in
// warp-private SMEM, so the 32 gathers in the inner loop are address-
// independent (deep MLP) instead of a serial meta->gather L2-latency chain.
__global__ void __launch_bounds__(256)
k_aggregate(const float* __restrict__ v)
{
    __shared__ int2 s_meta[8][32];
    int gtid = blockIdx.x * blockDim.x + threadIdx.x;
    int node = gtid >> 5;
    int lane = gtid & 31;
    int w    = threadIdx.x >> 5;
    if (node >= N_NODES) return;

    int p0 = __ldg(&g_rowptr[node]);
    int p1 = __ldg(&g_rowptr[node + 1]);

    const uint2* in = reinterpret_cast<const uint2*>(g_curh);  // 4 halfs per uint2
    float4 acc = make_float4(0.f, 0.f, 0.f, 0.f);

    for (int base = p0; base < p1; base += 32) {
        int idx = base + lane;
        if (idx < p1) s_meta[w][lane] = __ldg(&g_csr[idx]);
        __syncwarp();
        int cnt = min(32, p1 - base);
#pragma unroll 8
        for (int j = 0; j < cnt; j++) {
            int2 m = s_meta[w][j];                       // LDS.64 broadcast
            float f = __int_as_float(m.y);
            uint2 r = __ldg(&in[(size_t)m.x * 32 + lane]);
            float2 a = __half22float2(*reinterpret_cast<__half2*>(&r.x));
            float2 b = __half22float2(*reinterpret_cast<__half2*>(&r.y));
            acc.x += f * a.x; acc.y += f * a.y; acc.z += f * b.x; acc.w += f * b.y;
        }
        __syncwarp();
    }

    float4 vv = *reinterpret_cast<const float4*>(v + (size_t)node * DIM + lane * 4);
    acc.x += vv.x; acc.y += vv.y; acc.z += vv.z; acc.w += vv.w;
    *reinterpret_cast<float4*>(g_x + (size_t)node * DIM + lane * 4) = acc;
}

// out = relu(x @ A^T + b).  Block: 32x8 threads, 64 rows per block.
// Non-last layers also emit the fp16 copy for the next gather.
#define ROWS_PER_BLK 64
__global__ void __launch_bounds__(256, 2)
k_linear(const float* __restrict__ A, const float* __restrict__ b,
         float* __restrict__ dout, int last)
{
    extern __shared__ float smem[];
    float* As = smem;                  // 128*128
    float* xs = smem + DIM * DIM;      // 64*128

    int tx  = threadIdx.x;             // 0..31  (column quad)
    int ty  = threadIdx.y;             // 0..7   (row octet)
    int tid = ty * 32 + tx;

    // load A transposed: As[k*128 + j] = A[j*128 + k]
    for (int idx = tid; idx < DIM * DIM; idx += 256) {
        int k = idx >> 7, j = idx & 127;
        As[idx] = A[j * DIM + k];
    }
    int row0 = blockIdx.x * ROWS_PER_BLK;
    for (int idx = tid; idx < ROWS_PER_BLK * DIM; idx += 256) {
        int r = idx >> 7;
        xs[idx] = (row0 + r < N_NODES) ? g_x[(size_t)(row0 + r) * DIM + (idx & 127)] : 0.f;
    }
    __syncthreads();

    float4 acc[8];
#pragma unroll
    for (int r = 0; r < 8; r++) acc[r] = make_float4(0.f, 0.f, 0.f, 0.f);

    const float4* As4 = reinterpret_cast<const float4*>(As);
    const float*  xrow = xs + (ty * 8) * DIM;

#pragma unroll 8
    for (int k = 0; k < DIM; k++) {
        float4 a = As4[k * 32 + tx];
#pragma unroll
        for (int r = 0; r < 8; r++) {
            float xv = xrow[r * DIM + k];
            acc[r].x += a.x * xv;
            acc[r].y += a.y * xv;
            acc[r].z += a.z * xv;
            acc[r].w += a.w * xv;
        }
    }

    float4 bb = *reinterpret_cast<const float4*>(b + tx * 4);
#pragma unroll
    for (int r = 0; r < 8; r++) {
        int row = row0 + ty * 8 + r;
        if (row < N_NODES) {
            float4 o;
            o.x = fmaxf(acc[r].x + bb.x, 0.f);
            o.y = fmaxf(acc[r].y + bb.y, 0.f);
            o.z = fmaxf(acc[r].z + bb.z, 0.f);
            o.w = fmaxf(acc[r].w + bb.w, 0.f);
            if (last) {
                *reinterpret_cast<float4*>(dout + (size_t)row * DIM + tx * 4) = o;
            } else {
                __half2 h0 = __floats2half2_rn(o.x, o.y);
                __half2 h1 = __floats2half2_rn(o.z, o.w);
                uint2 raw;
                raw.x = *reinterpret_cast<unsigned*>(&h0);
                raw.y = *reinterpret_cast<unsigned*>(&h1);
                reinterpret_cast<uint2*>(g_curh)[row * 32 + tx] = raw;
            }
        }
    }
}

// ---------------------------------------------------------------------------
extern "C" void kernel_launch(void* const* d_in, const int* in_sizes, int n_in,
                              void* d_out, int out_size)
{
    const float* v     = (const float*)d_in[0];
    const float* e     = (const float*)d_in[1];
    const int*   src   = (const int*)d_in[2];
    const int*   dst   = (const int*)d_in[3];
    const float* A_w   = (const float*)d_in[4];
    const float* A_b   = (const float*)d_in[5];
    const float* rs    = (const float*)d_in[6];
    const float* sigma = (const float*)d_in[7];
    float* out = (float*)d_out;

    (void)in_sizes; (void)n_in; (void)out_size;

    const int SMEM_LIN = (DIM * DIM + ROWS_PER_BLK * DIM) * (int)sizeof(float); // 96KB
    cudaFuncSetAttribute(k_linear, cudaFuncAttributeMaxDynamicSharedMemorySize, SMEM_LIN);

    int gN = (N_NODES + 255) / 256;
    int gE = (N_EDGES + 255) / 256;

    // build CSR (per launch; inputs are constant so this is deterministic work)
    k_zero <<<gN, 256>>>();
    k_hist <<<gE, 256>>>(dst);
    k_scan1<<<N_CHUNKS, SCAN_BLK>>>();
    k_scan3<<<N_CHUNKS, SCAN_BLK>>>();
    k_fill <<<gE, 256>>>(src, dst, e, rs, sigma);
    k_v2h  <<<(N_NODES * 32 + 255) / 256, 256>>>(v);

    int aggBlocks = (N_NODES * 32 + 255) / 256;           // warp per node
    int linBlocks = (N_NODES + ROWS_PER_BLK - 1) / ROWS_PER_BLK;
    dim3 linDim(32, 8);

    for (int d = 0; d < DEPTH; d++) {
        k_aggregate<<<aggBlocks, 256>>>(v);
        k_linear<<<linBlocks, linDim, SMEM_LIN>>>(A_w, A_b, out, d == DEPTH - 1 ? 1 : 0);
    }
}